// round 1
// baseline (speedup 1.0000x reference)
#include <cuda_runtime.h>
#include <math.h>

#define N_ROWS 100000
#define NF 50
#define NB 16
#define NK 15
#define FPC 1e-4

#define TILE_N 128
#define THREADS 256
#define RT_THREADS 256

// Scratch (device globals only — no allocation allowed)
__device__ unsigned short g_comp[(size_t)N_ROWS * NF];   // 10 MB compressed bitmasks
__device__ int   g_cnt_bad[NF * NB];
__device__ int   g_cnt_good[NF * NB];
__device__ int   g_n1;
__device__ float g_wuse[NF * NB];

// ---------------------------------------------------------------------------
__global__ void zero_kernel() {
    int t = threadIdx.x;
    if (t < NF * NB) { g_cnt_bad[t] = 0; g_cnt_good[t] = 0; }
    if (t == 0) g_n1 = 0;
}

// ---------------------------------------------------------------------------
// Pass 1: stream x, compress each (n,f) row of 16 floats into a 16-bit mask,
// and reduce class-conditional counts per (f,b) via warp ballots.
__global__ void __launch_bounds__(THREADS)
reduce_compress_kernel(const float* __restrict__ x, const int* __restrict__ y) {
    __shared__ unsigned short sh_mask[TILE_N * NF];
    __shared__ int sh_bad[TILE_N];
    __shared__ int sh_hb[NF * NB];
    __shared__ int sh_hg[NF * NB];
    __shared__ int sh_n1;

    const int tid = threadIdx.x;
    const int n_base = blockIdx.x * TILE_N;

    for (int i = tid; i < NF * NB; i += THREADS) { sh_hb[i] = 0; sh_hg[i] = 0; }
    if (tid < TILE_N) {
        int n = n_base + tid;
        sh_bad[tid] = (n < N_ROWS) ? (y[n] == 1) : 0;
    }

    // Phase A: coalesced load + compress. pair p = n_local*NF + f,
    // address of floats = n_base*800 + p*16 (contiguous in p).
    const float4* xb = (const float4*)(x + (size_t)n_base * (NF * NB));
    #pragma unroll 5
    for (int it = 0; it < (TILE_N * NF) / THREADS; ++it) {
        int p = it * THREADS + tid;
        int n_local = p / NF;
        unsigned m = 0;
        if (n_base + n_local < N_ROWS) {
            float4 a = xb[p * 4 + 0];
            float4 b = xb[p * 4 + 1];
            float4 c = xb[p * 4 + 2];
            float4 d = xb[p * 4 + 3];
            m |= (a.x != 0.f) << 0;  m |= (a.y != 0.f) << 1;
            m |= (a.z != 0.f) << 2;  m |= (a.w != 0.f) << 3;
            m |= (b.x != 0.f) << 4;  m |= (b.y != 0.f) << 5;
            m |= (b.z != 0.f) << 6;  m |= (b.w != 0.f) << 7;
            m |= (c.x != 0.f) << 8;  m |= (c.y != 0.f) << 9;
            m |= (c.z != 0.f) << 10; m |= (c.w != 0.f) << 11;
            m |= (d.x != 0.f) << 12; m |= (d.y != 0.f) << 13;
            m |= (d.z != 0.f) << 14; m |= (d.w != 0.f) << 15;
            g_comp[(size_t)n_base * NF + p] = (unsigned short)m;
        }
        sh_mask[p] = (unsigned short)m;
    }
    __syncthreads();

    const int warp = tid >> 5;
    const int lane = tid & 31;

    // n1 (count of y==1 in tile): warp 0 only
    if (warp == 0) {
        int c = 0;
        #pragma unroll
        for (int s = 0; s < 4; s++)
            c += __popc(__ballot_sync(0xffffffffu, sh_bad[s * 32 + lane]));
        if (lane == 0) sh_n1 = c;
    }

    // Phase B: each warp owns feature f (strided); lanes cover 32 n's each sub-step.
    // LDS address stride = 50 halfwords = 25 words -> conflict-free.
    for (int f = warp; f < NF; f += THREADS / 32) {
        int cb[NB], cg[NB];
        #pragma unroll
        for (int b = 0; b < NB; b++) { cb[b] = 0; cg[b] = 0; }
        #pragma unroll
        for (int s = 0; s < 4; s++) {
            int nl = s * 32 + lane;
            unsigned m = sh_mask[nl * NF + f];
            int bad = sh_bad[nl];
            int good = bad ^ 1;
            #pragma unroll
            for (int b = 0; b < NB; b++) {
                unsigned bit = (m >> b) & 1u;
                unsigned pb = __ballot_sync(0xffffffffu, bit & (unsigned)bad);
                unsigned pg = __ballot_sync(0xffffffffu, bit & (unsigned)good);
                cb[b] += __popc(pb);
                cg[b] += __popc(pg);
            }
        }
        if (lane == 0) {
            #pragma unroll
            for (int b = 0; b < NB; b++) {
                sh_hb[f * NB + b] += cb[b];
                sh_hg[f * NB + b] += cg[b];
            }
        }
    }
    __syncthreads();

    for (int i = tid; i < NF * NB; i += THREADS) {
        if (sh_hb[i]) atomicAdd(&g_cnt_bad[i], sh_hb[i]);
        if (sh_hg[i]) atomicAdd(&g_cnt_good[i], sh_hg[i]);
    }
    if (tid == 0 && sh_n1) atomicAdd(&g_n1, sh_n1);
}

// ---------------------------------------------------------------------------
// Tiny WLS kernel: one thread per feature, double precision.
// Writes woe and wls_adj_woe to the output tail, and w_use (nan->0) to g_wuse.
__global__ void wls_kernel(float* __restrict__ out) {
    int f = threadIdx.x;
    if (f >= NF) return;

    const int n1 = g_n1;
    const int n0 = N_ROWS - n1;

    double woe[NB];
    double tot[NB];
    #pragma unroll
    for (int b = 0; b < NB; b++) {
        int cb = g_cnt_bad[f * NB + b];
        int cg = g_cnt_good[f * NB + b];
        woe[b] = log((double)cb / (double)n1 + FPC) - log((double)cg / (double)n0 + FPC);
        tot[b] = (double)(cb + cg) / (double)N_ROWS;
    }

    // pct = normalized total_pct[:,1:], w = woe[:,1:]
    double s = 0.0;
    for (int k = 0; k < NK; k++) s += tot[k + 1];
    double pct[NK], w[NK];
    for (int k = 0; k < NK; k++) { pct[k] = tot[k + 1] / s; w[k] = woe[k + 1]; }

    // first nonzero pct index (argmax of cumsum==1; 0 if all zero)
    int first = 0;
    for (int k = 0; k < NK; k++) { if (pct[k] != 0.0) { first = k; break; } }

    double idxv[NK], ind[NK];
    for (int k = 0; k < NK; k++) {
        double v = (double)(k + 1 - first);
        if (v < 0.0) v = 0.0;
        idxv[k] = v;
        ind[k]  = (v != 0.0) ? 1.0 : 0.0;
    }

    // ---- Fit 1: X = [ind, idx], 2x2 weighted normal equations
    double s00 = 0, s01 = 0, s11 = 0, r0 = 0, r1v = 0;
    for (int k = 0; k < NK; k++) {
        double p = pct[k], u = ind[k], v = idxv[k];
        s00 += p * u * u; s01 += p * u * v; s11 += p * v * v;
        r0 += p * u * w[k]; r1v += p * v * w[k];
    }
    double det2 = s00 * s11 - s01 * s01;
    double c10 = (s11 * r0 - s01 * r1v) / det2;
    double c11 = (s00 * r1v - s01 * r0) / det2;
    double fit1[NK];
    for (int k = 0; k < NK; k++) fit1[k] = ind[k] * c10 + idxv[k] * c11;

    // ---- Fit 2: X = [ind, idx, idx^2], 3x3 via Cramer
    double a00 = 0, a01 = 0, a02 = 0, a11 = 0, a12 = 0, a22 = 0;
    double b0 = 0, b1 = 0, b2 = 0;
    for (int k = 0; k < NK; k++) {
        double p = pct[k], u = ind[k], v = idxv[k], v2 = v * v;
        a00 += p * u * u; a01 += p * u * v; a02 += p * u * v2;
        a11 += p * v * v; a12 += p * v * v2; a22 += p * v2 * v2;
        b0 += p * u * w[k]; b1 += p * v * w[k]; b2 += p * v2 * w[k];
    }
    double det3 = a00 * (a11 * a22 - a12 * a12)
                - a01 * (a01 * a22 - a12 * a02)
                + a02 * (a01 * a12 - a11 * a02);
    double c20 = (b0 * (a11 * a22 - a12 * a12)
                - a01 * (b1 * a22 - a12 * b2)
                + a02 * (b1 * a12 - a11 * b2)) / det3;
    double c21 = (a00 * (b1 * a22 - a12 * b2)
                - b0 * (a01 * a22 - a12 * a02)
                + a02 * (a01 * b2 - b1 * a02)) / det3;
    double c22 = (a00 * (a11 * b2 - b1 * a12)
                - a01 * (a01 * b2 - b1 * a02)
                + b0 * (a01 * a12 - a11 * a02)) / det3;
    double fit2[NK];
    for (int k = 0; k < NK; k++)
        fit2[k] = ind[k] * c20 + idxv[k] * c21 + idxv[k] * idxv[k] * c22;

    // ---- R^2 + blend
    double mean = 0;
    for (int k = 0; k < NK; k++) mean += w[k] * pct[k];
    double sst = 0, sse1 = 0, sse2 = 0;
    for (int k = 0; k < NK; k++) {
        double d = w[k] - mean; sst += d * d * pct[k];
        d = fit1[k] - w[k]; sse1 += d * d * pct[k];
        d = fit2[k] - w[k]; sse2 += d * d * pct[k];
    }
    double r1 = 1.0 - sse1 / sst;
    double r2 = 1.0 - sse2 / sst;

    float* out_woe = out + (size_t)N_ROWS * NF;           // 5,000,000
    float* out_adj = out_woe + NF * NB;                   // +800

    #pragma unroll
    for (int b = 0; b < NB; b++) out_woe[f * NB + b] = (float)woe[b];

    float a0 = (float)woe[0];
    out_adj[f * NB + 0] = a0;
    g_wuse[f * NB + 0] = isnan(a0) ? 0.0f : a0;
    for (int k = 0; k < NK; k++) {
        double a = (fit1[k] * r1 + fit2[k] * r2) / (r1 + r2);
        float af = (float)a;
        out_adj[f * NB + 1 + k] = af;
        g_wuse[f * NB + 1 + k] = isnan(af) ? 0.0f : af;
    }
}

// ---------------------------------------------------------------------------
// Pass 2: rt[n,f] = sum_b mask_bit(b) * w_use[f,b] via nibble LUT.
// Each thread handles 4 consecutive (n,f) pairs (uint64 mask load, float4 store).
__global__ void __launch_bounds__(RT_THREADS)
rt_kernel(float* __restrict__ out) {
    __shared__ float lut[NF * 64];
    const int tid = threadIdx.x;
    for (int e = tid; e < NF * 64; e += RT_THREADS) {
        int f = e >> 6;
        int pos = (e >> 4) & 3;
        int v = e & 15;
        const float* wp = &g_wuse[f * NB + pos * 4];
        float sv = 0.0f;
        if (v & 1) sv += wp[0];
        if (v & 2) sv += wp[1];
        if (v & 4) sv += wp[2];
        if (v & 8) sv += wp[3];
        lut[e] = sv;
    }
    __syncthreads();

    const unsigned TOTAL_Q = (unsigned)(N_ROWS * NF / 4);  // 1,250,000
    unsigned q = blockIdx.x * RT_THREADS + tid;
    if (q >= TOTAL_Q) return;

    unsigned long long packed =
        *(const unsigned long long*)&g_comp[(size_t)q * 4];

    float r[4];
    #pragma unroll
    for (int i = 0; i < 4; i++) {
        unsigned p = q * 4 + i;
        int f = (int)(p % NF);
        unsigned m = (unsigned)(packed >> (16 * i)) & 0xffffu;
        r[i] = lut[f * 64 +      (m & 15)]
             + lut[f * 64 + 16 + ((m >> 4) & 15)]
             + lut[f * 64 + 32 + ((m >> 8) & 15)]
             + lut[f * 64 + 48 + (m >> 12)];
    }
    float4 rv = make_float4(r[0], r[1], r[2], r[3]);
    *(float4*)(out + (size_t)q * 4) = rv;
}

// ---------------------------------------------------------------------------
extern "C" void kernel_launch(void* const* d_in, const int* in_sizes, int n_in,
                              void* d_out, int out_size) {
    const float* x = (const float*)d_in[0];
    const int* y = (const int*)d_in[1];
    float* out = (float*)d_out;

    zero_kernel<<<1, NF * NB>>>();

    int blocks = (N_ROWS + TILE_N - 1) / TILE_N;
    reduce_compress_kernel<<<blocks, THREADS>>>(x, y);

    wls_kernel<<<1, 64>>>(out);

    int rt_blocks = (N_ROWS * NF / 4 + RT_THREADS - 1) / RT_THREADS;
    rt_kernel<<<rt_blocks, RT_THREADS>>>(out);
}